// round 16
// baseline (speedup 1.0000x reference)
#include <cuda_runtime.h>
#include <cuda_fp16.h>
#include <cstdint>

// PIPNet fused gather + MLP via mma.sync (HMMA) single-fp16.
//   out[p] = relu(concat(g1[il[p]], g2[ir[p]]) @ W1^T + b1) @ W2^T + b2
//
// R15: R14's pair-local structure + cross-tile software pipelining.
// CTA = 128 threads = 2 pair-groups; tile = 64 pairs; double-buffered A
// (2 x 16KB). Persistent grid (592 CTAs, ~26 tiles each): each group
// interleaves tile T+1's gather (LDG+cvt+STS, 2 iters per ks) inside tile
// T's MMA mainloop, so gather latency hides under the same warp's tensor
// work. Warp shape / fragments / B path identical to R14.

#define NTHREADS 128
#define GRID_CTAS 592

// smem layout (bytes): two 64x128 fp16 A buffers (rows 256B, swizzled chunks).
#define SM_A0   0
#define SM_A1   16384
#define SM_B1   32768
#define SM_W2   33280
#define SM_RED  33792
#define SMEM_TOTAL (33792 + 512 + 128)

// W1 fp16 fragment buffer: [nb(2)][ks(8)][pr(4)][lane(32)][reg(4)] u32 = 32KB.
__device__ uint32_t g_Wfrag[2 * 8 * 4 * 32 * 4];

static __device__ __forceinline__ uint32_t smem_u32(const void* p) {
    uint32_t a;
    asm("{ .reg .u64 t; cvta.to.shared.u64 t, %1; cvt.u32.u64 %0, t; }"
        : "=r"(a) : "l"(p));
    return a;
}

static __device__ __forceinline__ uint32_t tile_off(int row, int chunk) {
    return (uint32_t)row * 256u + (uint32_t)((chunk ^ (row & 7)) * 16);
}

static __device__ __forceinline__ void ldsm_x4(uint32_t* r, uint32_t addr) {
    asm volatile("ldmatrix.sync.aligned.m8n8.x4.shared.b16 {%0,%1,%2,%3}, [%4];"
                 : "=r"(r[0]), "=r"(r[1]), "=r"(r[2]), "=r"(r[3]) : "r"(addr));
}
static __device__ __forceinline__ void mma_f16(float* c, const uint32_t* a,
                                               uint32_t b0, uint32_t b1) {
    asm volatile("mma.sync.aligned.m16n8k16.row.col.f32.f16.f16.f32 "
                 "{%0,%1,%2,%3}, {%4,%5,%6,%7}, {%8,%9}, {%0,%1,%2,%3};"
                 : "+f"(c[0]), "+f"(c[1]), "+f"(c[2]), "+f"(c[3])
                 : "r"(a[0]), "r"(a[1]), "r"(a[2]), "r"(a[3]), "r"(b0), "r"(b1));
}

static __device__ __forceinline__ uint32_t pack_h2(__half a, __half b) {
    __half2 h = __halves2half2(a, b);
    return *(uint32_t*)&h;
}

// Pair-local named barrier: group g (64 threads), barrier id g+1.
static __device__ __forceinline__ void bar_grp(int g) {
    asm volatile("bar.sync %0, 64;" :: "r"(g + 1) : "memory");
}

// ---- Prep: write W1's fp16 mma B-fragments in fragment order ----
// NON-trans ldmatrix x4 reg j at lane l holds the f16x2 pair
// W1h[n][k], W1h[n][k+1] with
//   n = nb*64 + pr*16 + (j>>1)*8 + (l>>2),  k = ks*16 + (j&1)*8 + 2*(l&3).
__global__ void pipnet_prep_wfrag(const float* __restrict__ W1) {
    int flat = blockIdx.x * blockDim.x + threadIdx.x;   // 8192 entries
    if (flat >= 8192) return;
    int j  = flat & 3;
    int l  = (flat >> 2) & 31;
    int pr = (flat >> 7) & 3;
    int ks = (flat >> 9) & 7;
    int nb = (flat >> 12) & 1;
    int n = nb * 64 + pr * 16 + ((j >> 1) << 3) + (l >> 2);
    int k = ks * 16 + ((j & 1) << 3) + 2 * (l & 3);
    g_Wfrag[flat] = pack_h2(__float2half_rn(W1[n * 128 + k]),
                            __float2half_rn(W1[n * 128 + k + 1]));
}

__global__ __launch_bounds__(NTHREADS, 4)
void pipnet_hmma_kernel(const float* __restrict__ g1,
                        const float* __restrict__ g2,
                        const int* __restrict__ idxL,
                        const int* __restrict__ idxR,
                        const float* __restrict__ b1,
                        const float* __restrict__ W2,
                        const float* __restrict__ b2,
                        float* __restrict__ out,
                        int P, int Nnodes)
{
    extern __shared__ char smem[];
    const uint32_t sbase = smem_u32(smem);
    const int tid = threadIdx.x;
    const int wid = tid >> 5;
    const int lid = tid & 31;
    const int g  = wid >> 1;            // pair-group (0-1): rows g*32..+31
    const int nb = wid & 1;             // half / n-block within group

    const int numTiles = (P + 63) >> 6;

    // ---- Stage b1 / W2 ----
    if (tid < 128) {
        *(float*)(smem + SM_B1 + tid * 4) = b1[tid];
        *(float*)(smem + SM_W2 + tid * 4) = W2[tid];
    }
    const float b2v = b2[0];
    __syncthreads();

    // gather constants (uniform per warp)
    const int* __restrict__ idx = nb ? idxR : idxL;
    const float* __restrict__ gsrc = nb ? g2 : g1;
    const int lane_in = lid & 15;       // float4 slot within the node row
    const int r0 = g * 32;

    // compute constants
    const int n_base = nb * 64;
    const int gl = lid & 7;
    const int grp = lid >> 3;
    const uint4* __restrict__ Wf = (const uint4*)g_Wfrag;
    const float* s_b1 = (const float*)(smem + SM_B1);
    const float* s_w2 = (const float*)(smem + SM_W2);
    float* red = (float*)(smem + SM_RED);

    // one gather iteration i (0..15) of tile t into buffer buf
    auto gather_iter = [&](long long t, char* buf, int i) {
        int r = r0 + i * 2 + (lid >> 4);
        long long pair = t * 64 + r;
        if (pair >= P) pair = P - 1;
        int srcRow = idx[pair];
        if (srcRow < 0) srcRow = 0;
        if (srcRow >= Nnodes) srcRow = Nnodes - 1;
        const float4* src = (const float4*)(gsrc + (long long)srcRow * 64);
        float4 v = src[lane_in];
        uint2 hv = make_uint2(pack_h2(__float2half_rn(v.x), __float2half_rn(v.y)),
                              pack_h2(__float2half_rn(v.z), __float2half_rn(v.w)));
        uint32_t off = tile_off(r, nb * 8 + (lane_in >> 1)) + (lane_in & 1) * 8;
        *(uint2*)(buf + off) = hv;
    };

    long long t = blockIdx.x;
    if (t >= numTiles) return;

    // ---- Prologue: gather tile t into buf0 ----
    #pragma unroll
    for (int i = 0; i < 16; ++i) gather_iter(t, smem + SM_A0, i);
    bar_grp(g);

    int cur = 0;
    while (true) {
        long long tn = t + GRID_CTAS;
        const bool have_next = (tn < numTiles);
        const uint32_t aT = sbase + (cur ? SM_A1 : SM_A0);
        char* nbuf = smem + (cur ? SM_A0 : SM_A1);

        float acc[2][8][4];
        #pragma unroll
        for (int mt = 0; mt < 2; ++mt)
            #pragma unroll
            for (int c = 0; c < 8; ++c)
                #pragma unroll
                for (int q = 0; q < 4; ++q) acc[mt][c][q] = 0.f;

        // ---- Mainloop with interleaved next-tile gather (2 iters per ks) ----
        #pragma unroll
        for (int ks = 0; ks < 8; ++ks) {
            int kc = ks * 2;
            uint32_t af0[4], af1[4];
            {
                int row0 = r0 + (grp & 1) * 8 + gl;
                ldsm_x4(af0, aT + tile_off(row0, kc + (grp >> 1)));
                ldsm_x4(af1, aT + tile_off(row0 + 16, kc + (grp >> 1)));
            }
            if (have_next) {
                gather_iter(tn, nbuf, ks * 2);
                gather_iter(tn, nbuf, ks * 2 + 1);
            }
            const uint4* wk = Wf + ((nb * 8 + ks) * 4) * 32 + lid;
            #pragma unroll
            for (int pr = 0; pr < 4; ++pr) {
                uint4 vb = wk[pr * 32];
                mma_f16(acc[0][pr * 2],     af0, vb.x, vb.y);
                mma_f16(acc[0][pr * 2 + 1], af0, vb.z, vb.w);
                mma_f16(acc[1][pr * 2],     af1, vb.x, vb.y);
                mma_f16(acc[1][pr * 2 + 1], af1, vb.z, vb.w);
            }
        }

        // ---- Epilogue: bias + ReLU + W2 dot, quad reduce, group combine ----
        const int q2 = (lid & 3) * 2;
        #pragma unroll
        for (int mt = 0; mt < 2; ++mt) {
            float pa = 0.f, pb = 0.f;   // rows r0+mt*16+(lid>>2) and +8
            #pragma unroll
            for (int c = 0; c < 8; ++c) {
                int n = n_base + c * 8 + q2;
                float b0 = s_b1[n], b1x = s_b1[n + 1];
                float w0 = s_w2[n], w1x = s_w2[n + 1];
                pa += fmaxf(acc[mt][c][0] + b0, 0.f) * w0
                    + fmaxf(acc[mt][c][1] + b1x, 0.f) * w1x;
                pb += fmaxf(acc[mt][c][2] + b0, 0.f) * w0
                    + fmaxf(acc[mt][c][3] + b1x, 0.f) * w1x;
            }
            pa += __shfl_xor_sync(0xffffffffu, pa, 1);
            pa += __shfl_xor_sync(0xffffffffu, pa, 2);
            pb += __shfl_xor_sync(0xffffffffu, pb, 1);
            pb += __shfl_xor_sync(0xffffffffu, pb, 2);
            if ((lid & 3) == 0) {
                int ra = r0 + mt * 16 + (lid >> 2);
                red[ra * 2 + nb] = pa;
                red[(ra + 8) * 2 + nb] = pb;
            }
        }
        // bar: red staged by both warps; also orders next-tile STS before
        // the partner's reads in the next mainloop.
        bar_grp(g);

        if (nb == 0) {
            int r = r0 + lid;
            float s = red[r * 2] + red[r * 2 + 1] + b2v;
            long long p = t * 64 + r;
            if (p < P) out[p] = s;
        }
        if (!have_next) break;
        // bar: protect red (write-after-read) and publish nbuf completion.
        bar_grp(g);
        t = tn;
        cur ^= 1;
    }
}

extern "C" void kernel_launch(void* const* d_in, const int* in_sizes, int n_in,
                              void* d_out, int out_size) {
    const float* g1  = (const float*)d_in[0];   // graph1_x [N,64]
    const float* g2  = (const float*)d_in[1];   // graph2_x [N,64]
    const int*   il  = (const int*)d_in[2];     // idx_left  [P] int32
    const int*   ir  = (const int*)d_in[3];     // idx_right [P] int32
    const float* W1  = (const float*)d_in[4];   // [128,128]
    const float* b1  = (const float*)d_in[5];   // [128]
    const float* W2  = (const float*)d_in[6];   // [1,128]
    const float* b2  = (const float*)d_in[7];   // [1]
    float*       out = (float*)d_out;           // [P,1]

    int P = in_sizes[2];
    int Nnodes = in_sizes[0] / 64;
    int numTiles = (P + 63) >> 6;
    int grid = numTiles < GRID_CTAS ? numTiles : GRID_CTAS;

    pipnet_prep_wfrag<<<32, 256>>>(W1);

    cudaFuncSetAttribute(pipnet_hmma_kernel,
                         cudaFuncAttributeMaxDynamicSharedMemorySize, SMEM_TOTAL);
    pipnet_hmma_kernel<<<grid, NTHREADS, SMEM_TOTAL>>>(
        g1, g2, il, ir, b1, W2, b2, out, P, Nnodes);
}

// round 17
// speedup vs baseline: 1.7361x; 1.7361x over previous
#include <cuda_runtime.h>
#include <cuda_fp16.h>
#include <cstdint>

// PIPNet fused gather + MLP via mma.sync (HMMA) single-fp16.
//   out[p] = relu(concat(g1[il[p]], g2[ir[p]]) @ W1^T + b1) @ W2^T + b2
//
// R16: R14 (pair-local barriers, 128-pair tile, warp 32m x 64n) made
// persistent (296 CTAs = 2/SM) with L2 prefetch of the NEXT tile's gather
// lines. Prefetch costs no registers and no scoreboard entry, so unlike
// R15's inline gather (which stalled the mainloop) it hides DRAM latency
// without touching the compute structure. Source rows ride in one register
// per lane and are distributed by __shfl at gather time.

#define MTILE 128
#define NTHREADS 256
#define GRID_CTAS 296

// smem layout (bytes): A tile 128x128 fp16 (rows 256B, swizzled 16B chunks).
#define SM_A    0
#define SM_B1   32768
#define SM_W2   33280
#define SM_RED  33792
#define SMEM_TOTAL (33792 + 1024 + 128)

// W1 fp16 fragment buffer: [nb(2)][ks(8)][pr(4)][lane(32)][reg(4)] u32 = 32KB.
__device__ uint32_t g_Wfrag[2 * 8 * 4 * 32 * 4];

static __device__ __forceinline__ uint32_t smem_u32(const void* p) {
    uint32_t a;
    asm("{ .reg .u64 t; cvta.to.shared.u64 t, %1; cvt.u32.u64 %0, t; }"
        : "=r"(a) : "l"(p));
    return a;
}

static __device__ __forceinline__ uint32_t tile_off(int row, int chunk) {
    return (uint32_t)row * 256u + (uint32_t)((chunk ^ (row & 7)) * 16);
}

static __device__ __forceinline__ void ldsm_x4(uint32_t* r, uint32_t addr) {
    asm volatile("ldmatrix.sync.aligned.m8n8.x4.shared.b16 {%0,%1,%2,%3}, [%4];"
                 : "=r"(r[0]), "=r"(r[1]), "=r"(r[2]), "=r"(r[3]) : "r"(addr));
}
static __device__ __forceinline__ void mma_f16(float* c, const uint32_t* a,
                                               uint32_t b0, uint32_t b1) {
    asm volatile("mma.sync.aligned.m16n8k16.row.col.f32.f16.f16.f32 "
                 "{%0,%1,%2,%3}, {%4,%5,%6,%7}, {%8,%9}, {%0,%1,%2,%3};"
                 : "+f"(c[0]), "+f"(c[1]), "+f"(c[2]), "+f"(c[3])
                 : "r"(a[0]), "r"(a[1]), "r"(a[2]), "r"(a[3]), "r"(b0), "r"(b1));
}

static __device__ __forceinline__ uint32_t pack_h2(__half a, __half b) {
    __half2 h = __halves2half2(a, b);
    return *(uint32_t*)&h;
}

// Pairwise named barrier: 2 warps (64 threads), id 1..4 per pair.
static __device__ __forceinline__ void bar_pair(int pair_id) {
    asm volatile("bar.sync %0, 64;" :: "r"(pair_id + 1) : "memory");
}

// ---- Prep: write W1's fp16 mma B-fragments in fragment order ----
// NON-trans ldmatrix x4 reg j at lane l holds the f16x2 pair
// W1h[n][k], W1h[n][k+1] with
//   n = nb*64 + pr*16 + (j>>1)*8 + (l>>2),  k = ks*16 + (j&1)*8 + 2*(l&3).
__global__ void pipnet_prep_wfrag(const float* __restrict__ W1) {
    int flat = blockIdx.x * blockDim.x + threadIdx.x;   // 8192 entries
    if (flat >= 8192) return;
    int j  = flat & 3;
    int l  = (flat >> 2) & 31;
    int pr = (flat >> 7) & 3;
    int ks = (flat >> 9) & 7;
    int nb = (flat >> 12) & 1;
    int n = nb * 64 + pr * 16 + ((j >> 1) << 3) + (l >> 2);
    int k = ks * 16 + ((j & 1) << 3) + 2 * (l & 3);
    g_Wfrag[flat] = pack_h2(__float2half_rn(W1[n * 128 + k]),
                            __float2half_rn(W1[n * 128 + k + 1]));
}

__global__ __launch_bounds__(NTHREADS, 2)
void pipnet_hmma_kernel(const float* __restrict__ g1,
                        const float* __restrict__ g2,
                        const int* __restrict__ idxL,
                        const int* __restrict__ idxR,
                        const float* __restrict__ b1,
                        const float* __restrict__ W2,
                        const float* __restrict__ b2,
                        float* __restrict__ out,
                        int P, int Nnodes)
{
    extern __shared__ char smem[];
    const uint32_t sbase = smem_u32(smem);
    const int tid = threadIdx.x;
    const int wid = tid >> 5;
    const int lid = tid & 31;
    const int w  = wid >> 1;            // pair id (0-3): rows w*32..+31
    const int nb = wid & 1;             // half / n-block within pair

    const int numTiles = (P + MTILE - 1) / MTILE;

    // ---- Stage b1 / W2 (one-time CTA barrier) ----
    if (tid < 128) {
        *(float*)(smem + SM_B1 + tid * 4) = b1[tid];
        *(float*)(smem + SM_W2 + tid * 4) = W2[tid];
    }
    const float b2v = b2[0];
    __syncthreads();

    // gather constants (uniform per warp)
    const int* __restrict__ idx = nb ? idxR : idxL;
    const float* __restrict__ gsrc = nb ? g2 : g1;
    const int lane_in = lid & 15;       // float4 slot within the node row
    const int r0 = w * 32;

    // compute constants
    const int m_base = r0;
    const int n_base = nb * 64;
    const int gl = lid & 7;
    const int grp = lid >> 3;
    const uint4* __restrict__ Wf = (const uint4*)g_Wfrag;
    const float* s_b1 = (const float*)(smem + SM_B1);
    const float* s_w2 = (const float*)(smem + SM_W2);
    float* red = (float*)(smem + SM_RED);

    // Lane lid holds the source row for tile-row r0+lid of its half.
    auto load_src = [&](long long tt) -> int {
        long long pair = tt * MTILE + r0 + lid;
        if (pair >= P) pair = P - 1;
        int s = idx[pair];
        if (s < 0) s = 0;
        if (s >= Nnodes) s = Nnodes - 1;
        return s;
    };

    long long t = blockIdx.x;
    if (t >= numTiles) return;
    int srcCur = load_src(t);

    while (true) {
        long long tn = t + GRID_CTAS;
        const bool have_next = (tn < numTiles);
        int srcNext = 0;
        if (have_next) srcNext = load_src(tn);   // in flight during gather

        // ---- Gather tile t: rows r0..r0+31, half nb; sources via shfl ----
        #pragma unroll
        for (int i = 0; i < 16; ++i) {
            int r = r0 + i * 2 + (lid >> 4);
            int sr = __shfl_sync(0xffffffffu, srcCur, i * 2 + (lid >> 4));
            const float4* src = (const float4*)(gsrc + (long long)sr * 64);
            float4 v = src[lane_in];
            uint2 hv = make_uint2(pack_h2(__float2half_rn(v.x), __float2half_rn(v.y)),
                                  pack_h2(__float2half_rn(v.z), __float2half_rn(v.w)));
            uint32_t off = tile_off(r, nb * 8 + (lane_in >> 1)) + (lane_in & 1) * 8;
            *(uint2*)(smem + SM_A + off) = hv;
        }

        // ---- Prefetch next tile's 64 lines to L2 (per-lane distinct lines) ----
        if (have_next) {
            const char* pb = (const char*)(gsrc + (long long)srcNext * 64);
            asm volatile("prefetch.global.L2 [%0];" :: "l"(pb));
            asm volatile("prefetch.global.L2 [%0];" :: "l"(pb + 128));
        }
        bar_pair(w);   // both halves of rows r0..r0+31 are in smem

        // ---- HMMA mainloop: warp = 32m x 64n ----
        float acc[2][8][4];
        #pragma unroll
        for (int mt = 0; mt < 2; ++mt)
            #pragma unroll
            for (int c = 0; c < 8; ++c)
                #pragma unroll
                for (int q = 0; q < 4; ++q) acc[mt][c][q] = 0.f;

        const uint32_t aT = sbase + SM_A;
        #pragma unroll
        for (int ks = 0; ks < 8; ++ks) {
            int kc = ks * 2;
            uint32_t af0[4], af1[4];
            {
                int row0 = m_base + (grp & 1) * 8 + gl;
                ldsm_x4(af0, aT + tile_off(row0, kc + (grp >> 1)));
                ldsm_x4(af1, aT + tile_off(row0 + 16, kc + (grp >> 1)));
            }
            const uint4* wk = Wf + ((nb * 8 + ks) * 4) * 32 + lid;
            #pragma unroll
            for (int pr = 0; pr < 4; ++pr) {
                uint4 vb = wk[pr * 32];
                mma_f16(acc[0][pr * 2],     af0, vb.x, vb.y);
                mma_f16(acc[0][pr * 2 + 1], af0, vb.z, vb.w);
                mma_f16(acc[1][pr * 2],     af1, vb.x, vb.y);
                mma_f16(acc[1][pr * 2 + 1], af1, vb.z, vb.w);
            }
        }

        // ---- Epilogue: bias + ReLU + W2 dot, quad reduce, pair combine ----
        const int q2 = (lid & 3) * 2;
        #pragma unroll
        for (int mt = 0; mt < 2; ++mt) {
            float pa = 0.f, pb2 = 0.f;   // rows m_base+mt*16+(lid>>2) and +8
            #pragma unroll
            for (int c = 0; c < 8; ++c) {
                int n = n_base + c * 8 + q2;
                float b0 = s_b1[n], b1x = s_b1[n + 1];
                float w0 = s_w2[n], w1x = s_w2[n + 1];
                pa  += fmaxf(acc[mt][c][0] + b0, 0.f) * w0
                     + fmaxf(acc[mt][c][1] + b1x, 0.f) * w1x;
                pb2 += fmaxf(acc[mt][c][2] + b0, 0.f) * w0
                     + fmaxf(acc[mt][c][3] + b1x, 0.f) * w1x;
            }
            pa  += __shfl_xor_sync(0xffffffffu, pa, 1);
            pa  += __shfl_xor_sync(0xffffffffu, pa, 2);
            pb2 += __shfl_xor_sync(0xffffffffu, pb2, 1);
            pb2 += __shfl_xor_sync(0xffffffffu, pb2, 2);
            if ((lid & 3) == 0) {
                int ra = m_base + mt * 16 + (lid >> 2);
                red[ra * 2 + nb] = pa;
                red[(ra + 8) * 2 + nb] = pb2;
            }
        }
        bar_pair(w);   // both n-halves staged; also MMA done -> A reusable

        if (nb == 0) {
            int r = m_base + lid;
            float s = red[r * 2] + red[r * 2 + 1] + b2v;
            long long p = t * MTILE + r;
            if (p < P) out[p] = s;
        }
        if (!have_next) break;
        srcCur = srcNext;
        t = tn;
    }
}

extern "C" void kernel_launch(void* const* d_in, const int* in_sizes, int n_in,
                              void* d_out, int out_size) {
    const float* g1  = (const float*)d_in[0];   // graph1_x [N,64]
    const float* g2  = (const float*)d_in[1];   // graph2_x [N,64]
    const int*   il  = (const int*)d_in[2];     // idx_left  [P] int32
    const int*   ir  = (const int*)d_in[3];     // idx_right [P] int32
    const float* W1  = (const float*)d_in[4];   // [128,128]
    const float* b1  = (const float*)d_in[5];   // [128]
    const float* W2  = (const float*)d_in[6];   // [1,128]
    const float* b2  = (const float*)d_in[7];   // [1]
    float*       out = (float*)d_out;           // [P,1]

    int P = in_sizes[2];
    int Nnodes = in_sizes[0] / 64;
    int numTiles = (P + MTILE - 1) / MTILE;
    int grid = numTiles < GRID_CTAS ? numTiles : GRID_CTAS;

    pipnet_prep_wfrag<<<32, 256>>>(W1);

    cudaFuncSetAttribute(pipnet_hmma_kernel,
                         cudaFuncAttributeMaxDynamicSharedMemorySize, SMEM_TOTAL);
    pipnet_hmma_kernel<<<grid, NTHREADS, SMEM_TOTAL>>>(
        g1, g2, il, ir, b1, W2, b2, out, P, Nnodes);
}